// round 4
// baseline (speedup 1.0000x reference)
#include <cuda_runtime.h>
#include <math.h>

#define BB 32
#define LL 4096
#define DD 1024
#define SPLITS 16
#define CHUNK (LL / SPLITS)   // 256 rows per block
#define NTHREADS 256
#define RGROUP 8
#define NEG_INF_F (-1e30f)
#define P2_PARTS (SPLITS + 1) // 1 pooled block + 16 weights blocks per batch

// Scratch (allocation-free rule: __device__ globals)
__device__ float g_scores[BB * LL];                 // raw masked scores (512 KB)
__device__ float g_pm[BB * SPLITS];                 // per-split running max
__device__ float g_ps[BB * SPLITS];                 // per-split running sum
__device__ float g_pacc[(size_t)BB * SPLITS * DD];  // per-split weighted acc (2 MB)

__global__ __launch_bounds__(NTHREADS)
void uda_pass1(const float* __restrict__ seq,
               const float* __restrict__ vec,
               const int* __restrict__ mask) {
    const int blk   = blockIdx.x;        // b*SPLITS + split
    const int b     = blk / SPLITS;
    const int split = blk % SPLITS;
    const int l0    = split * CHUNK;
    const int tid   = threadIdx.x;
    const int wid   = tid >> 5;
    const int lane  = tid & 31;

    __shared__ float sm_part[RGROUP][NTHREADS];   // 8 KB
    __shared__ float sm_score[RGROUP];

    // Each thread owns 4 consecutive d-values (float4).
    const float4 v4 = reinterpret_cast<const float4*>(vec + (size_t)b * DD)[tid];

    float m = -INFINITY;
    float s = 0.0f;
    float4 acc = make_float4(0.f, 0.f, 0.f, 0.f);

    const float4* seqp = reinterpret_cast<const float4*>(seq + (size_t)b * LL * DD);
    const int* mrow = mask + (size_t)b * LL;

    for (int g = 0; g < CHUNK; g += RGROUP) {
        // Load 8 rows' worth of this thread's float4 (MLP=8)
        float4 x[RGROUP];
#pragma unroll
        for (int i = 0; i < RGROUP; i++)
            x[i] = seqp[(size_t)(l0 + g + i) * (DD / 4) + tid];

        // Partial dot products into shared
#pragma unroll
        for (int i = 0; i < RGROUP; i++)
            sm_part[i][tid] = x[i].x * v4.x + x[i].y * v4.y + x[i].z * v4.z + x[i].w * v4.w;
        __syncthreads();

        // Warp `wid` reduces row `wid` (8 warps <-> 8 rows), conflict-free reads
        {
            float r = 0.0f;
#pragma unroll
            for (int k = 0; k < NTHREADS / 32; k++)
                r += sm_part[wid][lane + 32 * k];
#pragma unroll
            for (int off = 16; off; off >>= 1)
                r += __shfl_xor_sync(0xffffffffu, r, off);
            if (lane == 0) {
                const int row = l0 + g + wid;
                if (mrow[row] == 0) r = NEG_INF_F;
                sm_score[wid] = r;
                g_scores[(size_t)b * LL + row] = r;   // for weights output
            }
        }
        __syncthreads();

        // Online softmax update (replicated, deterministic across all threads)
        float sc[RGROUP];
        float mnew = m;
#pragma unroll
        for (int i = 0; i < RGROUP; i++) {
            sc[i] = sm_score[i];
            mnew = fmaxf(mnew, sc[i]);
        }
        const float f = __expf(m - mnew);   // exp(-inf - finite) = 0 handles init
        s *= f;
        acc.x *= f; acc.y *= f; acc.z *= f; acc.w *= f;
#pragma unroll
        for (int i = 0; i < RGROUP; i++) {
            const float w = __expf(sc[i] - mnew);
            s += w;
            acc.x += w * x[i].x;
            acc.y += w * x[i].y;
            acc.z += w * x[i].z;
            acc.w += w * x[i].w;
        }
        m = mnew;
    }

    if (tid == 0) { g_pm[blk] = m; g_ps[blk] = s; }
    reinterpret_cast<float4*>(g_pacc + (size_t)blk * DD)[tid] = acc;
}

// Wide pass2: 544 blocks. Per batch: block 0 -> pooled[b,:],
// blocks 1..16 -> weights[b, (part-1)*256 .. ].
__global__ __launch_bounds__(NTHREADS)
void uda_pass2(float* __restrict__ out) {
    const int b    = blockIdx.x / P2_PARTS;
    const int part = blockIdx.x % P2_PARTS;
    const int tid  = threadIdx.x;

    // Global max / sum across splits (32 scalars, L2-resident, replicated)
    float pm[SPLITS];
    float M = -INFINITY;
#pragma unroll
    for (int i = 0; i < SPLITS; i++) {
        pm[i] = g_pm[b * SPLITS + i];
        M = fmaxf(M, pm[i]);
    }
    float S = 0.0f;
    float fac[SPLITS];
#pragma unroll
    for (int i = 0; i < SPLITS; i++) {
        fac[i] = __expf(pm[i] - M);
        S += g_ps[b * SPLITS + i] * fac[i];
    }
    const float invS = 1.0f / S;

    if (part == 0) {
        // pooled[b, :]  (output region 0: B*D floats)
        float4 acc = make_float4(0.f, 0.f, 0.f, 0.f);
#pragma unroll
        for (int i = 0; i < SPLITS; i++) {
            const float4 p =
                reinterpret_cast<const float4*>(g_pacc + (size_t)(b * SPLITS + i) * DD)[tid];
            const float f = fac[i];
            acc.x += f * p.x; acc.y += f * p.y; acc.z += f * p.z; acc.w += f * p.w;
        }
        acc.x *= invS; acc.y *= invS; acc.z *= invS; acc.w *= invS;
        reinterpret_cast<float4*>(out + (size_t)b * DD)[tid] = acc;
    } else {
        // weights[b, chunk]  (output region 1: B*L floats, after pooled)
        const int l = (part - 1) * NTHREADS + tid;
        const float sc = g_scores[(size_t)b * LL + l];
        out[(size_t)BB * DD + (size_t)b * LL + l] = __expf(sc - M) * invS;
    }
}

extern "C" void kernel_launch(void* const* d_in, const int* in_sizes, int n_in,
                              void* d_out, int out_size) {
    const float* seq  = (const float*)d_in[0];
    const float* vec  = (const float*)d_in[1];
    const int*   mask = (const int*)d_in[2];
    float* out = (float*)d_out;

    uda_pass1<<<BB * SPLITS, NTHREADS>>>(seq, vec, mask);
    uda_pass2<<<BB * P2_PARTS, NTHREADS>>>(out);
}

// round 6
// speedup vs baseline: 1.1709x; 1.1709x over previous
#include <cuda_runtime.h>
#include <math.h>

#define BB 32
#define LL 4096
#define DD 1024
#define SPLITS 16
#define CHUNK (LL / SPLITS)   // 256 rows per block
#define NTHREADS 256
#define RGROUP 8
#define NEG_INF_F (-1e30f)

// Scratch (allocation-free rule: __device__ globals)
__device__ float g_scores[BB * LL];                 // raw masked scores (512 KB)
__device__ float g_pm[BB * SPLITS];                 // per-split running max
__device__ float g_ps[BB * SPLITS];                 // per-split running sum
__device__ float g_pacc[(size_t)BB * SPLITS * DD];  // per-split weighted acc (2 MB)

__global__ __launch_bounds__(NTHREADS)
void uda_pass1(const float* __restrict__ seq,
               const float* __restrict__ vec,
               const int* __restrict__ mask) {
    const int blk   = blockIdx.x;        // b*SPLITS + split
    const int b     = blk / SPLITS;
    const int split = blk % SPLITS;
    const int l0    = split * CHUNK;
    const int tid   = threadIdx.x;
    const int wid   = tid >> 5;
    const int lane  = tid & 31;

    __shared__ float sm_part[RGROUP][NTHREADS];   // 8 KB
    __shared__ float sm_score[RGROUP];

    // Each thread owns 4 consecutive d-values (float4).
    const float4 v4 = reinterpret_cast<const float4*>(vec + (size_t)b * DD)[tid];

    float m = -INFINITY;
    float s = 0.0f;
    float4 acc = make_float4(0.f, 0.f, 0.f, 0.f);

    const float4* seqp = reinterpret_cast<const float4*>(seq + (size_t)b * LL * DD);
    const int* mrow = mask + (size_t)b * LL;

    for (int g = 0; g < CHUNK; g += RGROUP) {
        // Load 8 rows' worth of this thread's float4 (MLP=8)
        float4 x[RGROUP];
#pragma unroll
        for (int i = 0; i < RGROUP; i++)
            x[i] = seqp[(size_t)(l0 + g + i) * (DD / 4) + tid];

        // Partial dot products into shared
#pragma unroll
        for (int i = 0; i < RGROUP; i++)
            sm_part[i][tid] = x[i].x * v4.x + x[i].y * v4.y + x[i].z * v4.z + x[i].w * v4.w;
        __syncthreads();

        // Warp `wid` reduces row `wid` (8 warps <-> 8 rows), conflict-free reads
        {
            float r = 0.0f;
#pragma unroll
            for (int k = 0; k < NTHREADS / 32; k++)
                r += sm_part[wid][lane + 32 * k];
#pragma unroll
            for (int off = 16; off; off >>= 1)
                r += __shfl_xor_sync(0xffffffffu, r, off);
            if (lane == 0) {
                const int row = l0 + g + wid;
                if (mrow[row] == 0) r = NEG_INF_F;
                sm_score[wid] = r;
                g_scores[(size_t)b * LL + row] = r;   // for weights output
            }
        }
        __syncthreads();

        // Online softmax update (replicated, deterministic across all threads)
        float sc[RGROUP];
        float mnew = m;
#pragma unroll
        for (int i = 0; i < RGROUP; i++) {
            sc[i] = sm_score[i];
            mnew = fmaxf(mnew, sc[i]);
        }
        const float f = __expf(m - mnew);   // exp(-inf - finite) = 0 handles init
        s *= f;
        acc.x *= f; acc.y *= f; acc.z *= f; acc.w *= f;
#pragma unroll
        for (int i = 0; i < RGROUP; i++) {
            const float w = __expf(sc[i] - mnew);
            s += w;
            acc.x += w * x[i].x;
            acc.y += w * x[i].y;
            acc.z += w * x[i].z;
            acc.w += w * x[i].w;
        }
        m = mnew;
    }

    if (tid == 0) { g_pm[blk] = m; g_ps[blk] = s; }
    reinterpret_cast<float4*>(g_pacc + (size_t)blk * DD)[tid] = acc;
}

// pass2 v3: grid = BB*2. part 0 -> pooled[b,:] (MLP=16),
// part 1 -> weights[b,:] with 4 float4 per thread (MLP=4).
__global__ __launch_bounds__(NTHREADS)
void uda_pass2(float* __restrict__ out) {
    const int b    = blockIdx.x >> 1;
    const int part = blockIdx.x & 1;
    const int tid  = threadIdx.x;

    // Global max / sum across splits. Vectorized: 4 + 4 independent LDG.128.
    const float4* pm4 = reinterpret_cast<const float4*>(g_pm + b * SPLITS);
    const float4* ps4 = reinterpret_cast<const float4*>(g_ps + b * SPLITS);
    float4 pmv[SPLITS / 4], psv[SPLITS / 4];
#pragma unroll
    for (int i = 0; i < SPLITS / 4; i++) { pmv[i] = pm4[i]; psv[i] = ps4[i]; }

    float M = -INFINITY;
#pragma unroll
    for (int i = 0; i < SPLITS / 4; i++) {
        M = fmaxf(M, fmaxf(fmaxf(pmv[i].x, pmv[i].y), fmaxf(pmv[i].z, pmv[i].w)));
    }
    float S = 0.0f;
    float fac[SPLITS];
#pragma unroll
    for (int i = 0; i < SPLITS / 4; i++) {
        fac[4 * i + 0] = __expf(pmv[i].x - M);
        fac[4 * i + 1] = __expf(pmv[i].y - M);
        fac[4 * i + 2] = __expf(pmv[i].z - M);
        fac[4 * i + 3] = __expf(pmv[i].w - M);
        S += psv[i].x * fac[4 * i + 0] + psv[i].y * fac[4 * i + 1] +
             psv[i].z * fac[4 * i + 2] + psv[i].w * fac[4 * i + 3];
    }
    const float invS = 1.0f / S;

    if (part == 0) {
        // pooled[b, :]  (output region 0: B*D floats), 16 independent loads
        float4 acc = make_float4(0.f, 0.f, 0.f, 0.f);
#pragma unroll
        for (int i = 0; i < SPLITS; i++) {
            const float4 p =
                reinterpret_cast<const float4*>(g_pacc + (size_t)(b * SPLITS + i) * DD)[tid];
            const float f = fac[i];
            acc.x += f * p.x; acc.y += f * p.y; acc.z += f * p.z; acc.w += f * p.w;
        }
        acc.x *= invS; acc.y *= invS; acc.z *= invS; acc.w *= invS;
        reinterpret_cast<float4*>(out + (size_t)b * DD)[tid] = acc;
    } else {
        // weights[b, :]: 4096 floats = 1024 float4; 4 float4 per thread (MLP=4)
        const float4* sc4 = reinterpret_cast<const float4*>(g_scores + (size_t)b * LL);
        float4* w4 = reinterpret_cast<float4*>(out + (size_t)BB * DD + (size_t)b * LL);
        float4 sc[4];
#pragma unroll
        for (int k = 0; k < 4; k++)
            sc[k] = sc4[tid + k * NTHREADS];
#pragma unroll
        for (int k = 0; k < 4; k++) {
            float4 w;
            w.x = __expf(sc[k].x - M) * invS;
            w.y = __expf(sc[k].y - M) * invS;
            w.z = __expf(sc[k].z - M) * invS;
            w.w = __expf(sc[k].w - M) * invS;
            w4[tid + k * NTHREADS] = w;
        }
    }
}

extern "C" void kernel_launch(void* const* d_in, const int* in_sizes, int n_in,
                              void* d_out, int out_size) {
    const float* seq  = (const float*)d_in[0];
    const float* vec  = (const float*)d_in[1];
    const int*   mask = (const int*)d_in[2];
    float* out = (float*)d_out;

    uda_pass1<<<BB * SPLITS, NTHREADS>>>(seq, vec, mask);
    uda_pass2<<<BB * 2, NTHREADS>>>(out);
}